// round 4
// baseline (speedup 1.0000x reference)
#include <cuda_runtime.h>
#include <math.h>

#define BB 64

// ---------------------------------------------------------------------------
// Scratch
// ---------------------------------------------------------------------------
__device__ float g_pooled1[BB * 3];
__device__ float g_attn1[BB * 8];
__device__ float g_w1[BB * 64 * 3 * 49];
__device__ float g_conv1[BB * 64 * 112 * 112];
__device__ float g_pool1[BB * 64 * 56 * 56];
__device__ float g_pooled2[BB * 64];
__device__ float g_attn2[BB * 8];
__device__ float g_w2[BB * 128 * 64 * 9];
__device__ float g_conv2[BB * 128 * 28 * 28];
__device__ float g_pool2[BB * 128 * 14 * 14];
__device__ float g_rc1[BB * 256 * 49];
__device__ float g_rc2[BB * 256 * 49];
__device__ float g_rs[BB * 256 * 49];
__device__ float g_y[BB * 256];

__device__ float g_sum1[64],  g_sq1[64],  g_sc1[64],  g_sh1[64];
__device__ float g_sum2[128], g_sq2[128], g_sc2[128], g_sh2[128];
__device__ float g_sumr1[256], g_sqr1[256], g_scr1[256], g_shr1[256];
__device__ float g_sumr2[256], g_sqr2[256], g_scr2[256], g_shr2[256];
__device__ float g_sums[256],  g_sqs[256],  g_scs[256],  g_shs[256];

__device__ float g_T[50 * 1024];
__device__ float g_M[50 * 256];
__device__ float g_b2[50];

// ---------------------------------------------------------------------------
// bn scale/shift
// ---------------------------------------------------------------------------
__global__ void k_bnscale(const float* __restrict__ g, const float* __restrict__ be,
                          float cnt, int stage, int C) {
    int c = blockIdx.x * blockDim.x + threadIdx.x;
    if (c >= C) return;
    float *su, *sq, *sc, *sh;
    switch (stage) {
        case 0:  su = g_sum1;  sq = g_sq1;  sc = g_sc1;  sh = g_sh1;  break;
        case 1:  su = g_sum2;  sq = g_sq2;  sc = g_sc2;  sh = g_sh2;  break;
        case 2:  su = g_sumr1; sq = g_sqr1; sc = g_scr1; sh = g_shr1; break;
        case 3:  su = g_sumr2; sq = g_sqr2; sc = g_scr2; sh = g_shr2; break;
        default: su = g_sums;  sq = g_sqs;  sc = g_scs;  sh = g_shs;  break;
    }
    float m = su[c] / cnt;
    float v = sq[c] / cnt - m * m;
    float s = g[c] * rsqrtf(v + 1e-5f);
    sc[c] = s;
    sh[c] = be[c] - m * s;
}

// per-channel stats of [B,256,49]; which: 0 -> rc1, 1 -> rc2
__global__ void k_chstats(int which) {
    const float* src = which ? g_rc2 : g_rc1;
    float* su = which ? g_sumr2 : g_sumr1;
    float* sq = which ? g_sqr2 : g_sqr1;
    int c = blockIdx.x;
    float s = 0.f, q = 0.f;
    for (int t = threadIdx.x; t < BB * 49; t += 128) {
        int b = t / 49, p = t - b * 49;
        float v = src[(b * 256 + c) * 49 + p];
        s += v; q += v * v;
    }
    for (int o = 16; o; o >>= 1) {
        s += __shfl_down_sync(0xffffffffu, s, o);
        q += __shfl_down_sync(0xffffffffu, q, o);
    }
    __shared__ float rs[4], rq[4];
    int w = threadIdx.x >> 5;
    if ((threadIdx.x & 31) == 0) { rs[w] = s; rq[w] = q; }
    __syncthreads();
    if (threadIdx.x == 0) {
        su[c] = rs[0] + rs[1] + rs[2] + rs[3];
        sq[c] = rq[0] + rq[1] + rq[2] + rq[3];
    }
}

// ---------------------------------------------------------------------------
// Stage-1 attention (block 0 also zeroes the stat accumulators)
// ---------------------------------------------------------------------------
__global__ void k_pooled1(const float* __restrict__ imgs) {
    int bc = blockIdx.x;
    int tid = threadIdx.x;
    if (bc == 0) {
        for (int i = tid; i < BB * 64; i += 256) g_pooled2[i] = 0.f;
        if (tid < 64)  { g_sum1[tid] = 0.f; g_sq1[tid] = 0.f; }
        if (tid < 128) { g_sum2[tid] = 0.f; g_sq2[tid] = 0.f; }
        if (tid < 256) { g_sums[tid] = 0.f; g_sqs[tid] = 0.f; }
    }
    const float* p = imgs + (long)bc * 50176;
    float s = 0.f;
    for (int i = tid; i < 50176; i += 256) s += p[i];
    __shared__ float red[256];
    red[tid] = s; __syncthreads();
    for (int o = 128; o; o >>= 1) { if (tid < o) red[tid] += red[tid + o]; __syncthreads(); }
    if (tid == 0) g_pooled1[bc] = red[0] * (1.f / 50176.f);
}

__global__ void k_attn1(const float* __restrict__ fc1, const float* __restrict__ fc2,
                        const float* __restrict__ fc2b) {
    int b = threadIdx.x;
    if (b >= BB) return;
    float p[3];
    for (int c = 0; c < 3; c++) p[c] = g_pooled1[b * 3 + c];
    float h[8];
    for (int j = 0; j < 8; j++) {
        float s = 0.f;
        for (int c = 0; c < 3; c++) s += p[c] * fc1[j * 3 + c];
        h[j] = fmaxf(s, 0.f);
    }
    float lg[8], mx = -1e30f;
    for (int k = 0; k < 8; k++) {
        float s = fc2b[k];
        for (int j = 0; j < 8; j++) s += h[j] * fc2[k * 8 + j];
        lg[k] = s; mx = fmaxf(mx, s);
    }
    float den = 0.f;
    for (int k = 0; k < 8; k++) { lg[k] = expf(lg[k] - mx); den += lg[k]; }
    float inv = 1.f / den;
    for (int k = 0; k < 8; k++) g_attn1[b * 8 + k] = lg[k] * inv;
}

__global__ void k_w1agg(const float* __restrict__ dy1) {
    int idx = blockIdx.x * 256 + threadIdx.x;
    if (idx >= BB * 9408) return;
    int b = idx / 9408, i = idx - b * 9408;
    float s = 0.f;
#pragma unroll
    for (int k = 0; k < 8; k++) s += g_attn1[b * 8 + k] * dy1[k * 9408 + i];
    g_w1[idx] = s;
}

// ---------------------------------------------------------------------------
// Conv1: 3->64, 7x7 s2 p3. Register-hoisted operands.
// Thread = 1 ow x 4 oh x 8 co. Tile 28w x 16h. grid (28, 8 cog, 64 b), block 128.
// ---------------------------------------------------------------------------
__global__ void __launch_bounds__(128) k_conv1(const float* __restrict__ imgs) {
    __shared__ __align__(16) float s_in[3 * 37 * 62];   // rows 37, pitch 62
    __shared__ __align__(16) float s_w[8 * 3 * 7 * 8];  // [co][ci][kh][8]
    __shared__ float s_stat[16];
    int b = blockIdx.z, cog = blockIdx.y;
    int tr = blockIdx.x >> 2, tc = blockIdx.x & 3;
    int oh0 = tr * 16, ow0 = tc * 28;
    int tid = threadIdx.x;

    for (int t = tid; t < 8 * 147; t += 128) {
        int co = t / 147, rem = t - co * 147;
        int ci = rem / 49, rem2 = rem - ci * 49;
        int kh = rem2 / 7, kw = rem2 - kh * 7;
        s_w[((co * 3 + ci) * 7 + kh) * 8 + kw] = g_w1[b * 9408 + (cog * 8 + co) * 147 + rem];
    }
    int ih0 = 2 * oh0 - 3, iw0 = 2 * ow0 - 3;
    for (int t = tid; t < 6882; t += 128) {
        int ci = t / 2294, rem = t - ci * 2294;
        int r = rem / 62, c = rem - r * 62;
        int ih = ih0 + r, iw = iw0 + c;
        float v = 0.f;
        if ((unsigned)ih < 224u && (unsigned)iw < 224u)
            v = imgs[((b * 3 + ci) * 224 + ih) * 224 + iw];
        s_in[t] = v;
    }
    if (tid < 16) s_stat[tid] = 0.f;
    __syncthreads();

    float acc[4][8];
#pragma unroll
    for (int j = 0; j < 4; j++)
#pragma unroll
        for (int co = 0; co < 8; co++) acc[j][co] = 0.f;

    int tx = tid % 28, ty = tid / 28;
    if (tid < 112) {
#pragma unroll 1
        for (int ci = 0; ci < 3; ci++) {
#pragma unroll 1
            for (int kh = 0; kh < 7; kh++) {
                int rbase = ci * 2294 + (8 * ty + kh) * 62 + 2 * tx;   // even
                float in[4][8];
#pragma unroll
                for (int j = 0; j < 4; j++) {
                    const float2* rp = (const float2*)(s_in + rbase + 124 * j);
#pragma unroll
                    for (int p = 0; p < 4; p++) {
                        float2 v = rp[p];
                        in[j][2 * p] = v.x; in[j][2 * p + 1] = v.y;
                    }
                }
#pragma unroll
                for (int co = 0; co < 8; co++) {
                    const float4* wp = (const float4*)(s_w + ((co * 3 + ci) * 7 + kh) * 8);
                    float4 wa = wp[0], wb = wp[1];
                    float w[7] = {wa.x, wa.y, wa.z, wa.w, wb.x, wb.y, wb.z};
#pragma unroll
                    for (int j = 0; j < 4; j++)
#pragma unroll
                        for (int kw = 0; kw < 7; kw++)
                            acc[j][co] += w[kw] * in[j][kw];
                }
            }
        }
#pragma unroll
        for (int co = 0; co < 8; co++) {
            long cb = ((long)(b * 64 + cog * 8 + co)) * 12544;
#pragma unroll
            for (int j = 0; j < 4; j++) {
                int oh = oh0 + 4 * ty + j;
                g_conv1[cb + oh * 112 + ow0 + tx] = acc[j][co];
            }
        }
    }
#pragma unroll
    for (int co = 0; co < 8; co++) {
        float s = acc[0][co] + acc[1][co] + acc[2][co] + acc[3][co];
        float q = acc[0][co] * acc[0][co] + acc[1][co] * acc[1][co]
                + acc[2][co] * acc[2][co] + acc[3][co] * acc[3][co];
        for (int o = 16; o; o >>= 1) {
            s += __shfl_down_sync(0xffffffffu, s, o);
            q += __shfl_down_sync(0xffffffffu, q, o);
        }
        if ((tid & 31) == 0) { atomicAdd(&s_stat[co], s); atomicAdd(&s_stat[8 + co], q); }
    }
    __syncthreads();
    if (tid < 8) {
        atomicAdd(&g_sum1[cog * 8 + tid], s_stat[tid]);
        atomicAdd(&g_sq1[cog * 8 + tid], s_stat[8 + tid]);
    }
}

// ---------------------------------------------------------------------------
// BN1 + maxpool3 s2 p1: 112->56, accumulate pooled2
// ---------------------------------------------------------------------------
__global__ void k_bnpool1() {
    int b = blockIdx.z, c = blockIdx.y;
    int p = blockIdx.x * 256 + threadIdx.x;
    float outv = 0.f;
    bool valid = (p < 3136);
    if (valid) {
        int oh = p / 56, ow = p - oh * 56;
        float sc = g_sc1[c], sh = g_sh1[c];
        const float* ip = g_conv1 + (long)(b * 64 + c) * 12544;
        float m = -1e30f;
#pragma unroll
        for (int r = 0; r < 3; r++) {
            int ih = 2 * oh - 1 + r;
            if ((unsigned)ih >= 112u) continue;
#pragma unroll
            for (int cc = 0; cc < 3; cc++) {
                int iw = 2 * ow - 1 + cc;
                if ((unsigned)iw >= 112u) continue;
                m = fmaxf(m, ip[ih * 112 + iw] * sc + sh);
            }
        }
        g_pool1[(b * 64 + c) * 3136 + p] = m;
        outv = m;
    }
    float s = valid ? outv : 0.f;
    for (int o = 16; o; o >>= 1) s += __shfl_down_sync(0xffffffffu, s, o);
    __shared__ float s_red;
    if (threadIdx.x == 0) s_red = 0.f;
    __syncthreads();
    if ((threadIdx.x & 31) == 0) atomicAdd(&s_red, s);
    __syncthreads();
    if (threadIdx.x == 0) atomicAdd(&g_pooled2[b * 64 + c], s_red);
}

// ---------------------------------------------------------------------------
// Stage-2 attention
// ---------------------------------------------------------------------------
__global__ void k_attn2(const float* __restrict__ fc1, const float* __restrict__ fc2,
                        const float* __restrict__ fc2b) {
    int b = threadIdx.x;
    if (b >= BB) return;
    float h[17];
    for (int j = 0; j < 17; j++) {
        float s = 0.f;
        for (int c = 0; c < 64; c++)
            s += (g_pooled2[b * 64 + c] * (1.f / 3136.f)) * fc1[j * 64 + c];
        h[j] = fmaxf(s, 0.f);
    }
    float lg[8], mx = -1e30f;
    for (int k = 0; k < 8; k++) {
        float s = fc2b[k];
        for (int j = 0; j < 17; j++) s += h[j] * fc2[k * 17 + j];
        lg[k] = s; mx = fmaxf(mx, s);
    }
    float den = 0.f;
    for (int k = 0; k < 8; k++) { lg[k] = expf(lg[k] - mx); den += lg[k]; }
    float inv = 1.f / den;
    for (int k = 0; k < 8; k++) g_attn2[b * 8 + k] = lg[k] * inv;
}

__global__ void k_w2agg(const float* __restrict__ dy2) {
    int idx = blockIdx.x * 256 + threadIdx.x;
    if (idx >= BB * 73728) return;
    int b = idx / 73728, i = idx - b * 73728;
    float s = 0.f;
#pragma unroll
    for (int k = 0; k < 8; k++) s += g_attn2[b * 8 + k] * dy2[k * 73728 + i];
    g_w2[idx] = s;
}

// ---------------------------------------------------------------------------
// Conv2: 64->128, 3x3 s2 p1: 56->28. Register-hoisted. grid (16 cog, 64 b), block 224.
// ---------------------------------------------------------------------------
__global__ void __launch_bounds__(224) k_conv2() {
    __shared__ __align__(16) float s_in[2 * 3364];      // 2 x 58x58 padded
    __shared__ __align__(16) float s_w[8 * 2 * 3 * 4];  // [co][ci][kh][4]
    __shared__ float s_stat[16];
    int b = blockIdx.y, cog = blockIdx.x;
    int tid = threadIdx.x;
    int tx = tid % 28, tyq = tid / 28;

    for (int t = tid; t < 2 * 3364; t += 224) s_in[t] = 0.f;
    if (tid < 16) s_stat[tid] = 0.f;
    __syncthreads();

    float acc[4][8];
#pragma unroll
    for (int j = 0; j < 4; j++)
#pragma unroll
        for (int co = 0; co < 8; co++) acc[j][co] = 0.f;

#pragma unroll 1
    for (int c0 = 0; c0 < 64; c0 += 2) {
        for (int t = tid; t < 2 * 3136; t += 224) {
            int ci = t / 3136, p = t - ci * 3136;
            int r = p / 56, c = p - r * 56;
            s_in[ci * 3364 + (r + 1) * 58 + (c + 1)] =
                g_pool1[(b * 64 + c0 + ci) * 3136 + p];
        }
        if (tid < 144) {
            int co = tid / 18, rem = tid - co * 18;
            int cil = rem / 9, k = rem - cil * 9;
            int kh = k / 3, kw = k - kh * 3;
            s_w[((co * 2 + cil) * 3 + kh) * 4 + kw] =
                g_w2[b * 73728 + (cog * 8 + co) * 576 + (c0 + cil) * 9 + k];
        }
        __syncthreads();
        if (tid < 196) {
#pragma unroll
            for (int ci = 0; ci < 2; ci++) {
#pragma unroll
                for (int kh = 0; kh < 3; kh++) {
                    int rbase = ci * 3364 + (8 * tyq + kh) * 58 + 2 * tx;  // even
                    float in[4][4];
#pragma unroll
                    for (int j = 0; j < 4; j++) {
                        const float2* rp = (const float2*)(s_in + rbase + 116 * j);
                        float2 v0 = rp[0], v1 = rp[1];
                        in[j][0] = v0.x; in[j][1] = v0.y; in[j][2] = v1.x; in[j][3] = v1.y;
                    }
#pragma unroll
                    for (int co = 0; co < 8; co++) {
                        const float4* wp = (const float4*)(s_w + ((co * 2 + ci) * 3 + kh) * 4);
                        float4 w = wp[0];
#pragma unroll
                        for (int j = 0; j < 4; j++) {
                            acc[j][co] += w.x * in[j][0];
                            acc[j][co] += w.y * in[j][1];
                            acc[j][co] += w.z * in[j][2];
                        }
                    }
                }
            }
        }
        __syncthreads();
    }

    if (tid < 196) {
#pragma unroll
        for (int co = 0; co < 8; co++) {
            int cb = (b * 128 + cog * 8 + co) * 784;
#pragma unroll
            for (int j = 0; j < 4; j++) {
                int oh = 4 * tyq + j;
                g_conv2[cb + oh * 28 + tx] = acc[j][co];
            }
        }
    }
#pragma unroll
    for (int co = 0; co < 8; co++) {
        float s = acc[0][co] + acc[1][co] + acc[2][co] + acc[3][co];
        float q = acc[0][co] * acc[0][co] + acc[1][co] * acc[1][co]
                + acc[2][co] * acc[2][co] + acc[3][co] * acc[3][co];
        for (int o = 16; o; o >>= 1) {
            s += __shfl_down_sync(0xffffffffu, s, o);
            q += __shfl_down_sync(0xffffffffu, q, o);
        }
        if ((tid & 31) == 0) { atomicAdd(&s_stat[co], s); atomicAdd(&s_stat[8 + co], q); }
    }
    __syncthreads();
    if (tid < 8) {
        atomicAdd(&g_sum2[cog * 8 + tid], s_stat[tid]);
        atomicAdd(&g_sq2[cog * 8 + tid], s_stat[8 + tid]);
    }
}

// ---------------------------------------------------------------------------
// BN2 + maxpool3 s2 p1: 28->14
// ---------------------------------------------------------------------------
__global__ void k_bnpool2() {
    int b = blockIdx.y, c = blockIdx.x;
    int p = threadIdx.x;
    if (p >= 196) return;
    int oh = p / 14, ow = p - oh * 14;
    float sc = g_sc2[c], sh = g_sh2[c];
    const float* ip = g_conv2 + (b * 128 + c) * 784;
    float m = -1e30f;
#pragma unroll
    for (int r = 0; r < 3; r++) {
        int ih = 2 * oh - 1 + r;
        if ((unsigned)ih >= 28u) continue;
#pragma unroll
        for (int cc = 0; cc < 3; cc++) {
            int iw = 2 * ow - 1 + cc;
            if ((unsigned)iw >= 28u) continue;
            m = fmaxf(m, ip[ih * 28 + iw] * sc + sh);
        }
    }
    g_pool2[(b * 128 + c) * 196 + p] = m;
}

// ---------------------------------------------------------------------------
// resconv1: 128->256 3x3 s2, 14->7. 4 batches/block. grid (8 cog, 16 bq), block 196.
// ---------------------------------------------------------------------------
__global__ void __launch_bounds__(196) k_resconv1(const float* __restrict__ w) {
    __shared__ __align__(16) float s_in[4 * 4 * 270];   // [bl][ci][15x18]
    __shared__ __align__(16) float s_w[32 * 4 * 3 * 4]; // [co][ci][kh][4]
    int bq = blockIdx.y, cog = blockIdx.x;
    int b0 = bq * 4;
    int tid = threadIdx.x;
    int px = tid % 49, yq = tid / 49;
    int oh = px / 7, ow = px - oh * 7;
    float acc[4][8];
#pragma unroll
    for (int bl = 0; bl < 4; bl++)
#pragma unroll
        for (int co = 0; co < 8; co++) acc[bl][co] = 0.f;

#pragma unroll 1
    for (int c0 = 0; c0 < 128; c0 += 4) {
        for (int t = tid; t < 4 * 4 * 270; t += 196) {
            int bl = t / 1080, rem = t - bl * 1080;
            int ci = rem / 270, pos = rem - ci * 270;
            int r = pos / 18, c = pos - r * 18;
            int ih = r - 1, iw = c - 1;
            float v = 0.f;
            if ((unsigned)ih < 14u && (unsigned)iw < 14u)
                v = g_pool2[((b0 + bl) * 128 + c0 + ci) * 196 + ih * 14 + iw];
            s_in[t] = v;
        }
        for (int t = tid; t < 32 * 36; t += 196) {
            int co = t / 36, rem = t - co * 36;
            int ci = rem / 9, k = rem - ci * 9;
            int kh = k / 3, kw = k - kh * 3;
            s_w[((co * 4 + ci) * 3 + kh) * 4 + kw] =
                w[(cog * 32 + co) * 1152 + (c0 + ci) * 9 + k];
        }
        __syncthreads();
#pragma unroll 1
        for (int ci = 0; ci < 4; ci++) {
#pragma unroll
            for (int kh = 0; kh < 3; kh++) {
                float in[4][3];
#pragma unroll
                for (int bl = 0; bl < 4; bl++) {
                    int base = bl * 1080 + ci * 270 + (2 * oh + kh) * 18 + 2 * ow;
                    in[bl][0] = s_in[base];
                    in[bl][1] = s_in[base + 1];
                    in[bl][2] = s_in[base + 2];
                }
#pragma unroll
                for (int co = 0; co < 8; co++) {
                    const float4* wp = (const float4*)(s_w + (((yq * 8 + co) * 4 + ci) * 3 + kh) * 4);
                    float4 wv = wp[0];
#pragma unroll
                    for (int bl = 0; bl < 4; bl++) {
                        acc[bl][co] += wv.x * in[bl][0];
                        acc[bl][co] += wv.y * in[bl][1];
                        acc[bl][co] += wv.z * in[bl][2];
                    }
                }
            }
        }
        __syncthreads();
    }
#pragma unroll
    for (int bl = 0; bl < 4; bl++)
#pragma unroll
        for (int co = 0; co < 8; co++)
            g_rc1[((b0 + bl) * 256 + cog * 32 + yq * 8 + co) * 49 + px] = acc[bl][co];
}

// ---------------------------------------------------------------------------
// resconv2: 256->256 3x3 s1, 7x7, bn+relu fused into staging. 4 batches/block.
// ---------------------------------------------------------------------------
__global__ void __launch_bounds__(196) k_resconv2(const float* __restrict__ w) {
    __shared__ __align__(16) float s_in[4 * 4 * 108];   // [bl][ci][9x12]
    __shared__ __align__(16) float s_w[32 * 4 * 3 * 4];
    int bq = blockIdx.y, cog = blockIdx.x;
    int b0 = bq * 4;
    int tid = threadIdx.x;
    int px = tid % 49, yq = tid / 49;
    int oh = px / 7, ow = px - oh * 7;
    float acc[4][8];
#pragma unroll
    for (int bl = 0; bl < 4; bl++)
#pragma unroll
        for (int co = 0; co < 8; co++) acc[bl][co] = 0.f;

#pragma unroll 1
    for (int c0 = 0; c0 < 256; c0 += 4) {
        for (int t = tid; t < 4 * 4 * 108; t += 196) {
            int bl = t / 432, rem = t - bl * 432;
            int ci = rem / 108, pos = rem - ci * 108;
            int r = pos / 12, c = pos - r * 12;
            int ih = r - 1, iw = c - 1;
            float v = 0.f;
            if ((unsigned)ih < 7u && (unsigned)iw < 7u) {
                float sc = g_scr1[c0 + ci], sh = g_shr1[c0 + ci];
                v = fmaxf(g_rc1[((b0 + bl) * 256 + c0 + ci) * 49 + ih * 7 + iw] * sc + sh, 0.f);
            }
            s_in[t] = v;
        }
        for (int t = tid; t < 32 * 36; t += 196) {
            int co = t / 36, rem = t - co * 36;
            int ci = rem / 9, k = rem - ci * 9;
            int kh = k / 3, kw = k - kh * 3;
            s_w[((co * 4 + ci) * 3 + kh) * 4 + kw] =
                w[(cog * 32 + co) * 2304 + (c0 + ci) * 9 + k];
        }
        __syncthreads();
#pragma unroll 1
        for (int ci = 0; ci < 4; ci++) {
#pragma unroll
            for (int kh = 0; kh < 3; kh++) {
                float in[4][3];
#pragma unroll
                for (int bl = 0; bl < 4; bl++) {
                    int base = bl * 432 + ci * 108 + (oh + kh) * 12 + ow;
                    in[bl][0] = s_in[base];
                    in[bl][1] = s_in[base + 1];
                    in[bl][2] = s_in[base + 2];
                }
#pragma unroll
                for (int co = 0; co < 8; co++) {
                    const float4* wp = (const float4*)(s_w + (((yq * 8 + co) * 4 + ci) * 3 + kh) * 4);
                    float4 wv = wp[0];
#pragma unroll
                    for (int bl = 0; bl < 4; bl++) {
                        acc[bl][co] += wv.x * in[bl][0];
                        acc[bl][co] += wv.y * in[bl][1];
                        acc[bl][co] += wv.z * in[bl][2];
                    }
                }
            }
        }
        __syncthreads();
    }
#pragma unroll
    for (int bl = 0; bl < 4; bl++)
#pragma unroll
        for (int co = 0; co < 8; co++)
            g_rc2[((b0 + bl) * 256 + cog * 32 + yq * 8 + co) * 49 + px] = acc[bl][co];
}

// ---------------------------------------------------------------------------
// shortcut 1x1 s2 (with inline stats)
// ---------------------------------------------------------------------------
__global__ void k_shortcut(const float* __restrict__ w) {
    int b = blockIdx.y, co = blockIdx.x;
    int tid = threadIdx.x;
    float acc = 0.f;
    if (tid < 49) {
        int oh = tid / 7, ow = tid - oh * 7;
        const float* wb = w + co * 128;
        for (int ci = 0; ci < 128; ci++)
            acc += wb[ci] * g_pool2[(b * 128 + ci) * 196 + (2 * oh) * 14 + 2 * ow];
        g_rs[(b * 256 + co) * 49 + tid] = acc;
    }
    float s = (tid < 49) ? acc : 0.f, q = s * s;
    for (int o = 16; o; o >>= 1) {
        s += __shfl_down_sync(0xffffffffu, s, o);
        q += __shfl_down_sync(0xffffffffu, q, o);
    }
    __shared__ float s_s[2], s_q[2];
    if ((tid & 31) == 0) { s_s[tid >> 5] = s; s_q[tid >> 5] = q; }
    __syncthreads();
    if (tid == 0) {
        atomicAdd(&g_sums[co], s_s[0] + s_s[1]);
        atomicAdd(&g_sqs[co], s_q[0] + s_q[1]);
    }
}

__global__ void k_resfinal() {
    int idx = blockIdx.x * 256 + threadIdx.x;
    if (idx >= BB * 256) return;
    int b = idx >> 8, c = idx & 255;
    float sc2 = g_scr2[c], sh2 = g_shr2[c], scs = g_scs[c], shs = g_shs[c];
    const float* p2 = g_rc2 + (b * 256 + c) * 49;
    const float* ps = g_rs + (b * 256 + c) * 49;
    float s = 0.f;
    for (int p = 0; p < 49; p++) {
        float v = p2[p] * sc2 + sh2 + ps[p] * scs + shs;
        s += fmaxf(v, 0.f);
    }
    g_y[idx] = s * (1.f / 49.f);
}

// ---------------------------------------------------------------------------
// Tail fold (softmax attention collapses to 1x1 conv: wo@wv)
// ---------------------------------------------------------------------------
__global__ void k_foldT(const float* __restrict__ fcw, const float* __restrict__ wo) {
    int idx = blockIdx.x * 256 + threadIdx.x;
    if (idx >= 50 * 1024) return;
    int i = idx / 1024, j = idx - i * 1024;
    float s = 0.f;
    for (int c = 0; c < 256; c++) s += fcw[i * 256 + c] * wo[c * 1024 + j];
    g_T[idx] = s;
}

__global__ void k_foldM(const float* __restrict__ wv) {
    int idx = blockIdx.x * 256 + threadIdx.x;
    if (idx >= 50 * 256) return;
    int i = idx / 256, c = idx - i * 256;
    float s = 0.f;
    for (int j = 0; j < 1024; j++) s += g_T[i * 1024 + j] * wv[j * 256 + c];
    g_M[idx] = s;
}

__global__ void k_foldb(const float* __restrict__ fcw, const float* __restrict__ bo,
                        const float* __restrict__ fcb) {
    int i = threadIdx.x;
    if (i >= 50) return;
    float s = 0.f;
    for (int c = 0; c < 256; c++) s += fcw[i * 256 + c] * bo[c];
    g_b2[i] = s + fcb[i];
}

__global__ void k_final(float* __restrict__ out) {
    int idx = blockIdx.x * 64 + threadIdx.x;
    if (idx >= BB * 50) return;
    int b = idx / 50, i = idx - b * 50;
    float s = g_b2[i];
    for (int c = 0; c < 256; c++) s += g_y[b * 256 + c] * g_M[i * 256 + c];
    out[idx] = s;
}

// ---------------------------------------------------------------------------
// Launch (k_conv1 is the 4th launch -> ncu profile target)
// ---------------------------------------------------------------------------
extern "C" void kernel_launch(void* const* d_in, const int* in_sizes, int n_in,
                              void* d_out, int out_size) {
    const float* imgs   = (const float*)d_in[0];
    const float* a1f1   = (const float*)d_in[1];
    const float* a1f2   = (const float*)d_in[2];
    const float* a1f2b  = (const float*)d_in[3];
    const float* dy1    = (const float*)d_in[4];
    const float* bn1g   = (const float*)d_in[5];
    const float* bn1b   = (const float*)d_in[6];
    const float* a2f1   = (const float*)d_in[7];
    const float* a2f2   = (const float*)d_in[8];
    const float* a2f2b  = (const float*)d_in[9];
    const float* dy2    = (const float*)d_in[10];
    const float* bn2g   = (const float*)d_in[11];
    const float* bn2b   = (const float*)d_in[12];
    const float* rc1w   = (const float*)d_in[13];
    const float* rbn1g  = (const float*)d_in[14];
    const float* rbn1b  = (const float*)d_in[15];
    const float* rc2w   = (const float*)d_in[16];
    const float* rbn2g  = (const float*)d_in[17];
    const float* rbn2b  = (const float*)d_in[18];
    const float* rsw    = (const float*)d_in[19];
    const float* rbnsg  = (const float*)d_in[20];
    const float* rbnsb  = (const float*)d_in[21];
    const float* wv     = (const float*)d_in[24];
    const float* wo     = (const float*)d_in[25];
    const float* bo     = (const float*)d_in[26];
    const float* fcw    = (const float*)d_in[27];
    const float* fcb    = (const float*)d_in[28];
    float* out = (float*)d_out;
    (void)in_sizes; (void)n_in; (void)out_size;

    // stage 1 front (also zeroes stat accumulators in k_pooled1)
    k_pooled1<<<192, 256>>>(imgs);
    k_attn1<<<1, 64>>>(a1f1, a1f2, a1f2b);
    k_w1agg<<<(BB * 9408 + 255) / 256, 256>>>(dy1);
    k_conv1<<<dim3(28, 8, BB), 128>>>(imgs);   // <- 4th launch (profiled)

    // tail fold (independent)
    k_foldT<<<200, 256>>>(fcw, wo);
    k_foldM<<<50, 256>>>(wv);
    k_foldb<<<1, 64>>>(fcw, bo, fcb);

    k_bnscale<<<1, 64>>>(bn1g, bn1b, 802816.f, 0, 64);
    k_bnpool1<<<dim3(13, 64, BB), 256>>>();

    // stage 2
    k_attn2<<<1, 64>>>(a2f1, a2f2, a2f2b);
    k_w2agg<<<(BB * 73728 + 255) / 256, 256>>>(dy2);
    k_conv2<<<dim3(16, BB), 224>>>();
    k_bnscale<<<1, 128>>>(bn2g, bn2b, 50176.f, 1, 128);
    k_bnpool2<<<dim3(128, BB), 196>>>();

    // residual block
    k_resconv1<<<dim3(8, BB / 4), 196>>>(rc1w);
    k_chstats<<<256, 128>>>(0);
    k_bnscale<<<1, 256>>>(rbn1g, rbn1b, 3136.f, 2, 256);
    k_resconv2<<<dim3(8, BB / 4), 196>>>(rc2w);
    k_chstats<<<256, 128>>>(1);
    k_shortcut<<<dim3(256, BB), 64>>>(rsw);
    k_bnscale<<<1, 256>>>(rbn2g, rbn2b, 3136.f, 3, 256);
    k_bnscale<<<1, 256>>>(rbnsg, rbnsb, 3136.f, 4, 256);
    k_resfinal<<<64, 256>>>();

    k_final<<<50, 64>>>(out);
}